// round 13
// baseline (speedup 1.0000x reference)
#include <cuda_runtime.h>
#include <cuda_fp16.h>
#include <cstdint>

// Problem constants
#define B_ 2
#define C_ 256
#define H_ 64
#define W_ 64
#define P_ 4096
#define N_ 4
#define K2_ 81
#define CTOT_ 324

// ---------------------------------------------------------------------------
// Device scratch (allocation-free per harness rules). Whole pyramid fp16.
// ---------------------------------------------------------------------------
__device__ __half g_l0[(size_t)B_*P_*64*64];  // 64 MiB
__device__ __half g_l1[(size_t)B_*P_*32*32];  // 16 MiB
__device__ __half g_l2[(size_t)B_*P_*16*16];  //  4 MiB
__device__ __half g_l3[(size_t)B_*P_*8*8];    //  1 MiB

// fp16 operands, layout [b][c][p] (same as inputs)
__device__ __half gA[(size_t)B_*C_*P_];
__device__ __half gB[(size_t)B_*C_*P_];

// ---------------------------------------------------------------------------
// PTX helpers (base sm_80-class features only)
// ---------------------------------------------------------------------------
__device__ __forceinline__ uint32_t smem_u32(const void* p) {
    uint32_t a;
    asm("{ .reg .u64 t; cvta.to.shared.u64 t, %1; cvt.u32.u64 %0, t; }" : "=r"(a) : "l"(p));
    return a;
}
__device__ __forceinline__ void cp16(uint32_t d, const void* s) {
    asm volatile("cp.async.cg.shared.global [%0], [%1], 16;" :: "r"(d), "l"(s));
}
__device__ __forceinline__ void cp_commit() {
    asm volatile("cp.async.commit_group;" ::: "memory");
}
__device__ __forceinline__ void ldsm4t(uint32_t* r, uint32_t a) {
    asm volatile("ldmatrix.sync.aligned.m8n8.x4.trans.shared.b16 {%0,%1,%2,%3}, [%4];"
        : "=r"(r[0]), "=r"(r[1]), "=r"(r[2]), "=r"(r[3]) : "r"(a));
}
__device__ __forceinline__ void mma16816(float* c, const uint32_t* a, const uint32_t* b) {
    asm volatile("mma.sync.aligned.m16n8k16.row.col.f32.f16.f16.f32 "
        "{%0,%1,%2,%3}, {%4,%5,%6,%7}, {%8,%9}, {%0,%1,%2,%3};"
        : "+f"(c[0]), "+f"(c[1]), "+f"(c[2]), "+f"(c[3])
        : "r"(a[0]), "r"(a[1]), "r"(a[2]), "r"(a[3]), "r"(b[0]), "r"(b[1]));
}

// XOR swizzle of 16B group index g within a 256B k-row
#define SWZ(g, k) (((g) & 8) | (((g) ^ (k)) & 7))

// ---------------------------------------------------------------------------
// Kernel 0: fp32 -> fp16, both tensors in one launch.
// ---------------------------------------------------------------------------
__global__ __launch_bounds__(256) void convert_kernel(
    const float* __restrict__ f1, const float* __restrict__ f2)
{
    const int which = blockIdx.y;
    const float* __restrict__ src = which ? f2 : f1;
    __half* __restrict__ dst = which ? gB : gA;

    size_t i = ((size_t)blockIdx.x * 256 + threadIdx.x) * 4;
    float4 v = *(const float4*)(src + i);
    __half2 h0 = __floats2half2_rn(v.x, v.y);
    __half2 h1 = __floats2half2_rn(v.z, v.w);
    *(uint2*)((unsigned char*)dst + i * 2) =
        make_uint2(*(uint32_t*)&h0, *(uint32_t*)&h1);
}

// ---------------------------------------------------------------------------
// Kernel 1: HMMA fp16 correlation GEMM + fused pool_l1 (validated r7-r10).
// ---------------------------------------------------------------------------
__global__ __launch_bounds__(256, 2) void gemm_hmma_kernel()
{
    __shared__ __align__(1024) unsigned char smem[24576];   // 3 x 8KB stages
    const uint32_t sbase = smem_u32(smem);

    const int tid  = threadIdx.x;
    const int lane = tid & 31;
    const int wid  = tid >> 5;
    const int nt = blockIdx.x, mt = blockIdx.y, b = blockIdx.z;
    const int warp_m = wid & 3, warp_n = wid >> 2;
    const int m0w = warp_m * 32, n0w = warp_n * 64;

    const int ck = tid >> 4;
    const int cg = tid & 15;
    const uint32_t cdst = ck * 256 + SWZ(cg, ck) * 16;
    const size_t gsrc_a = ((size_t)b * C_ + ck) * P_ + mt * 128 + cg * 8;
    const size_t gsrc_b = ((size_t)b * C_ + ck) * P_ + nt * 128 + cg * 8;

    auto prefetch = [&](int s, int c) {
        uint32_t st = sbase + s * 8192 + cdst;
        size_t koff = (size_t)c * 16 * P_;
        cp16(st +    0, gA + gsrc_a + koff);
        cp16(st + 4096, gB + gsrc_b + koff);
        cp_commit();
    };

    const int alk   = (lane & 7) | ((lane & 16) >> 1);
    const int amsel = (lane >> 3) & 1;
    const int bkrow = (lane & 7) | ((lane & 8));
    const int bngo  = (lane >> 4) & 1;

    float acc[2][8][4];
    #pragma unroll
    for (int i = 0; i < 2; i++)
        #pragma unroll
        for (int j = 0; j < 8; j++)
            #pragma unroll
            for (int q = 0; q < 4; q++) acc[i][j][q] = 0.0f;

    prefetch(0, 0);
    prefetch(1, 1);

    for (int c = 0; c < 16; c++) {
        if (c < 14) asm volatile("cp.async.wait_group 1;" ::: "memory");
        else        asm volatile("cp.async.wait_group 0;" ::: "memory");
        __syncthreads();
        if (c + 2 < 16) prefetch((c + 2) % 3, c + 2);

        uint32_t st = sbase + (c % 3) * 8192;

        uint32_t ah[2][4];
        #pragma unroll
        for (int i = 0; i < 2; i++) {
            int mg = (m0w >> 3) + i * 2 + amsel;
            ldsm4t(ah[i], st + alk * 256 + SWZ(mg, alk) * 16);
        }

        uint32_t bh[4][4];
        #pragma unroll
        for (int jp = 0; jp < 4; jp++) {
            int ng = (n0w >> 3) + jp * 2 + bngo;
            ldsm4t(bh[jp], st + 4096 + bkrow * 256 + SWZ(ng, bkrow) * 16);
        }

        #pragma unroll
        for (int i = 0; i < 2; i++)
            #pragma unroll
            for (int jp = 0; jp < 4; jp++)
                #pragma unroll
                for (int jq = 0; jq < 2; jq++)
                    mma16816(acc[i][jp * 2 + jq], ah[i], bh[jp] + jq * 2);
    }

    #pragma unroll
    for (int i = 0; i < 2; i++)
        #pragma unroll
        for (int j = 0; j < 8; j++)
            #pragma unroll
            for (int q = 0; q < 4; q++) acc[i][j][q] *= 0.0625f;

    const int qr = lane >> 2;
    const int qc = lane & 3;

    // l0 stores: fp16, one __half2 (4B) per row per j
    #pragma unroll
    for (int i = 0; i < 2; i++) {
        int m = mt * 128 + m0w + i * 16 + qr;
        size_t row0 = ((size_t)(b * P_ + m)) * P_;
        size_t row1 = ((size_t)(b * P_ + m + 8)) * P_;
        #pragma unroll
        for (int j = 0; j < 8; j++) {
            int nn = nt * 128 + n0w + j * 8 + qc * 2;
            *(__half2*)(g_l0 + row0 + nn) = __floats2half2_rn(acc[i][j][0], acc[i][j][1]);
            *(__half2*)(g_l0 + row1 + nn) = __floats2half2_rn(acc[i][j][2], acc[i][j][3]);
        }
    }

    // pool_l1: fp32 accumulation in smem, fp16 store
    __syncthreads();
    float* l1buf = (float*)smem;     // [128][33]
    if (warp_n == 0) {
        #pragma unroll
        for (int i = 0; i < 2; i++) {
            int mr = m0w + i * 16 + qr;
            #pragma unroll
            for (int j = 0; j < 8; j++) {
                int xp = j * 4 + qc;
                l1buf[mr * 33 + xp]       = acc[i][j][0] + acc[i][j][1];
                l1buf[(mr + 8) * 33 + xp] = acc[i][j][2] + acc[i][j][3];
            }
        }
    }
    __syncthreads();
    if (warp_n == 1) {
        #pragma unroll
        for (int i = 0; i < 2; i++) {
            int mr = m0w + i * 16 + qr;
            #pragma unroll
            for (int j = 0; j < 8; j++) {
                int xp = j * 4 + qc;
                l1buf[mr * 33 + xp]       += acc[i][j][0] + acc[i][j][1];
                l1buf[(mr + 8) * 33 + xp] += acc[i][j][2] + acc[i][j][3];
            }
        }
    }
    __syncthreads();
    {
        int m = tid >> 1, half = tid & 1;
        const float* sp = l1buf + m * 33 + half * 16;
        __half2 hv[8];
        #pragma unroll
        for (int q = 0; q < 8; q++)
            hv[q] = __floats2half2_rn(sp[2*q] * 0.25f, sp[2*q+1] * 0.25f);
        __half* dst = g_l1 + ((size_t)(b * P_ + mt * 128 + m)) * 1024 + nt * 32 + half * 16;
        *(uint4*)dst       = *(uint4*)&hv[0];
        *(uint4*)(dst + 8) = *(uint4*)&hv[4];
    }
}

// ---------------------------------------------------------------------------
// Kernel 2: fused pooling l1(fp16) -> l2(fp16) -> l3(fp16). One block per (b,p).
// Intermediates held fp32 in smem; only storage is rounded.
// ---------------------------------------------------------------------------
__global__ __launch_bounds__(256) void pool23_kernel()
{
    __shared__ float s1[1024];
    __shared__ float s2[256];
    const int bp = blockIdx.x;
    const int t = threadIdx.x;

    {
        uint2 r = *(const uint2*)(g_l1 + (size_t)bp * 1024 + t * 4);
        float2 a = __half22float2(*(__half2*)&r.x);
        float2 c = __half22float2(*(__half2*)&r.y);
        s1[t*4+0] = a.x; s1[t*4+1] = a.y; s1[t*4+2] = c.x; s1[t*4+3] = c.y;
    }
    __syncthreads();

    {
        int y = t >> 4, x = t & 15;
        const float* s = s1 + (2*y) * 32 + 2*x;
        float v = 0.25f * (s[0] + s[1] + s[32] + s[33]);
        s2[t] = v;                                   // fp32 for l3 accumulation
        g_l2[(size_t)bp * 256 + t] = __float2half(v);
    }
    __syncthreads();

    if (t < 64) {
        int y = t >> 3, x = t & 7;
        const float* s = s2 + (2*y) * 16 + 2*x;
        g_l3[(size_t)bp * 64 + t] =
            __float2half(0.25f * (s[0] + s[1] + s[16] + s[17]));
    }
}

// ---------------------------------------------------------------------------
// Kernel 3: window gather + bilinear, all 4 levels per warp, ALL-fp16 pyramid.
// Block = 2 p-values x 4 flow dirs (n in low warp bits) so the 4 queries that
// share p also share the block -> l1/l2/l3 patch lines hit L1.
// ---------------------------------------------------------------------------
__global__ __launch_bounds__(256) void gather_kernel(
    const float* __restrict__ coords, float* __restrict__ out)
{
    __shared__ float patch_s[8][104];
    __shared__ __align__(16) float out_s[8][CTOT_];

    const int wl   = threadIdx.x >> 5;
    const int lane = threadIdx.x & 31;

    const int n   = wl & 3;                          // flow dir in LOW bits
    const unsigned qid = blockIdx.x * 2u + (wl >> 2); // (b,p): 0..8191
    const int p = qid & (P_ - 1);
    const int b = qid >> 12;

    const float cx = coords[((size_t)((b * N_ + n) * 2 + 0)) * P_ + p];
    const float cy = coords[((size_t)((b * N_ + n) * 2 + 1)) * P_ + p];

    const int k1 = lane + 32, k2 = lane + 64;
    const int ix0 = lane / 9, iy0 = lane % 9;
    const int ix1 = k1 / 9,   iy1 = k1 % 9;
    const int ix2 = k2 / 9,   iy2 = k2 % 9;

    const int pj0 = lane / 10,      pi0 = lane % 10;
    const int pj1 = (lane+32) / 10, pi1 = (lane+32) % 10;
    const int pj2 = (lane+64) / 10, pi2 = (lane+64) % 10;
    const int pj3 = (lane+96) / 10, pi3 = (lane+96) % 10;

    float* pw = patch_s[wl];
    float* ow = out_s[wl];

    #pragma unroll
    for (int l = 0; l < 4; l++) {
        const int sz = 64 >> l;
        const float inv = 1.0f / (float)(1 << l);
        const __half* base;
        switch (l) {
            case 0:  base = g_l0 + (size_t)(b * P_ + p) * 4096; break;
            case 1:  base = g_l1 + (size_t)(b * P_ + p) * 1024; break;
            case 2:  base = g_l2 + (size_t)(b * P_ + p) * 256;  break;
            default: base = g_l3 + (size_t)(b * P_ + p) * 64;   break;
        }

        const float xs = cx * inv;
        const float ys = cy * inv;
        const float x0f = floorf(xs);
        const float y0f = floorf(ys);
        const float fx = xs - x0f;
        const float fy = ys - y0f;
        const int x0 = (int)x0f;
        const int y0 = (int)y0f;

        auto fetch = [&](int j, int i) -> float {
            int yy = y0 - 4 + j, xx = x0 - 4 + i;
            if ((unsigned)yy < (unsigned)sz && (unsigned)xx < (unsigned)sz)
                return __half2float(base[yy * sz + xx]);
            return 0.0f;
        };

        pw[lane]      = fetch(pj0, pi0);
        pw[lane + 32] = fetch(pj1, pi1);
        pw[lane + 64] = fetch(pj2, pi2);
        if (lane < 4) pw[lane + 96] = fetch(pj3, pi3);
        __syncwarp();

        const float w00 = (1.0f - fy) * (1.0f - fx);
        const float w01 = (1.0f - fy) * fx;
        const float w10 = fy * (1.0f - fx);
        const float w11 = fy * fx;
        float* ob = ow + l * K2_;

        {
            float v00 = pw[iy0*10 + ix0],     v01 = pw[iy0*10 + ix0 + 1];
            float v10 = pw[(iy0+1)*10 + ix0], v11 = pw[(iy0+1)*10 + ix0 + 1];
            ob[lane] = w00*v00 + w01*v01 + w10*v10 + w11*v11;
        }
        {
            float v00 = pw[iy1*10 + ix1],     v01 = pw[iy1*10 + ix1 + 1];
            float v10 = pw[(iy1+1)*10 + ix1], v11 = pw[(iy1+1)*10 + ix1 + 1];
            ob[k1] = w00*v00 + w01*v01 + w10*v10 + w11*v11;
        }
        if (k2 < K2_) {
            float v00 = pw[iy2*10 + ix2],     v01 = pw[iy2*10 + ix2 + 1];
            float v10 = pw[(iy2+1)*10 + ix2], v11 = pw[(iy2+1)*10 + ix2 + 1];
            ob[k2] = w00*v00 + w01*v01 + w10*v10 + w11*v11;
        }
        __syncwarp();
    }

    const float4* os = (const float4*)ow;
    float4* dst = (float4*)(out + ((size_t)((b * N_ + n) * P_ + p)) * CTOT_);
    dst[lane]      = os[lane];
    dst[lane + 32] = os[lane + 32];
    if (lane < 17) dst[lane + 64] = os[lane + 64];
}

// ---------------------------------------------------------------------------
extern "C" void kernel_launch(void* const* d_in, const int* in_sizes, int n_in,
                              void* d_out, int out_size)
{
    const float* f1     = (const float*)d_in[0];
    const float* f2     = (const float*)d_in[1];
    const float* coords = (const float*)d_in[2];
    float* out = (float*)d_out;

    // 0) fp32 -> fp16
    dim3 cgrid((B_ * C_ * P_) / (256 * 4), 2);
    convert_kernel<<<cgrid, 256>>>(f1, f2);

    // 1) HMMA fp16 correlation GEMM (+ fused pool_l1)
    dim3 gg(32, 32, 2);
    gemm_hmma_kernel<<<gg, 256>>>();

    // 2) fused pyramid tail (l2 + l3), all fp16 storage
    pool23_kernel<<<B_ * P_, 256>>>();

    // 3) gather: block = 2 p x 4 n
    gather_kernel<<<(B_ * P_) / 2, 256>>>(coords, out);
}